// round 11
// baseline (speedup 1.0000x reference)
#include <cuda_runtime.h>
#include <cuda_fp16.h>
#include <cstdint>
#include <math.h>

#define EDIM 128
#define NTH  256
#define TROWS 64   // rows per CTA tile (kernel 1)
#define BMAX 524288

// ---- kernel-1 dynamic smem byte offsets ----
#define B_HI    0u        // c hi plane [n=128][k=128] fp16 swizzled (32 KB)
#define A_HI    32768u    // x hi plane [m=64][k=128] fp16 (16 KB)
#define O_CSQ   49152u    // float[128]
#define O_RAD   49664u    // float[128]
#define O_XSQ   50176u    // float[64]
#define O_KEYP  50432u    // u32[64][8] = 2048
#define SMEM_K1 52480u

#define REFINE_T 2.5e-2f

// scratch for strength + index between the two kernels
__device__ float g_s[BMAX];
__device__ int   g_j[BMAX];

__device__ __forceinline__ uint32_t smem_u32(const void* p) {
    uint32_t a;
    asm("{ .reg .u64 t; cvta.to.shared.u64 t, %1; cvt.u32.u64 %0, t; }" : "=r"(a) : "l"(p));
    return a;
}
__device__ __forceinline__ uint32_t bswz(uint32_t n, uint32_t kc) {
    return n * 256u + ((((kc ^ n) & 7u) | (kc & 8u)) << 4);
}
__device__ __forceinline__ uint32_t pack_h2(float lo, float hi) {
    uint32_t r;
    asm("cvt.rn.f16x2.f32 %0, %1, %2;" : "=r"(r) : "f"(hi), "f"(lo));
    return r;
}
__device__ __forceinline__ void ldm_x4(uint32_t* r, uint32_t addr) {
    asm volatile("ldmatrix.sync.aligned.m8n8.x4.shared.b16 {%0,%1,%2,%3}, [%4];"
                 : "=r"(r[0]), "=r"(r[1]), "=r"(r[2]), "=r"(r[3]) : "r"(addr));
}
__device__ __forceinline__ void mma16816(float* d, const uint32_t* a, const uint32_t* b) {
    asm volatile("mma.sync.aligned.m16n8k16.row.col.f32.f16.f16.f32 "
                 "{%0,%1,%2,%3}, {%4,%5,%6,%7}, {%8,%9}, {%0,%1,%2,%3};"
                 : "+f"(d[0]), "+f"(d[1]), "+f"(d[2]), "+f"(d[3])
                 : "r"(a[0]), "r"(a[1]), "r"(a[2]), "r"(a[3]), "r"(b[0]), "r"(b[1]));
}
#define STS64A(addr, a, b) \
    asm volatile("st.shared.v2.b32 [%0], {%1,%2};" :: "r"(addr), "r"(a), "r"(b) : "memory")

__device__ __forceinline__ uint32_t f2ord(float f) {
    uint32_t u = __float_as_uint(f);
    return (u & 0x80000000u) ? ~u : (u | 0x80000000u);
}
__device__ __forceinline__ float ord2f(uint32_t o) {
    uint32_t u = (o & 0x80000000u) ? (o ^ 0x80000000u) : ~o;
    return __uint_as_float(u);
}
__device__ __forceinline__ float exact_d2(const float4* __restrict__ xp,
                                          const float4* __restrict__ cp) {
    float a0 = 0.f, a1 = 0.f;
#pragma unroll 8
    for (int q = 0; q < 32; q++) {
        float4 xv = __ldg(xp + q), cv = __ldg(cp + q);
        float t0 = xv.x - cv.x, t1 = xv.y - cv.y;
        float t2 = xv.z - cv.z, t3 = xv.w - cv.w;
        a0 = fmaf(t0, t0, a0); a1 = fmaf(t1, t1, a1);
        a0 = fmaf(t2, t2, a0); a1 = fmaf(t3, t3, a1);
    }
    return a0 + a1;
}
__device__ __forceinline__ void load_row_quads(float4* v, const float* __restrict__ base,
                                               long long row, int g) {
    const float4* gp = reinterpret_cast<const float4*>(base + row * EDIM) + g;
#pragma unroll
    for (int i = 0; i < 8; i++) v[i] = __ldg(gp + 4 * i);
}
// convert 8 float4s of a row -> fp16 hi plane; exact f32 row-sum to sqout
__device__ __forceinline__ void cvt_hi(uint32_t sb, uint32_t plane, int rowloc, int g,
                                       const float4* v, float* sqout) {
    float acc = 0.f;
#pragma unroll
    for (int i = 0; i < 8; i++) {
        float4 f = v[i];
        int c4 = g + 4 * i;
        uint32_t kc = (uint32_t)(c4 >> 1), hf = (uint32_t)(c4 & 1) * 8u;
        uint32_t h0 = pack_h2(f.x, f.y), h1 = pack_h2(f.z, f.w);
        acc = fmaf(f.x, f.x, acc); acc = fmaf(f.y, f.y, acc);
        acc = fmaf(f.z, f.z, acc); acc = fmaf(f.w, f.w, acc);
        STS64A(sb + plane + bswz((uint32_t)rowloc, kc) + hf, h0, h1);
    }
    acc += __shfl_xor_sync(0xffffffffu, acc, 8);
    acc += __shfl_xor_sync(0xffffffffu, acc, 16);
    if (g == 0) sqout[rowloc] = acc;
}

// ============================ kernel 1: argmin ============================
__global__ void __launch_bounds__(NTH, 3)
argmin_kernel(const float* __restrict__ xg, const float* __restrict__ cg,
              const float* __restrict__ radg, float* __restrict__ out,
              int Brows, int write_idx)
{
    extern __shared__ char smraw[];
    const uint32_t sb = smem_u32(smraw);
    float* csq  = (float*)(smraw + O_CSQ);
    float* rad  = (float*)(smraw + O_RAD);
    float* xsq  = (float*)(smraw + O_XSQ);
    uint32_t* keyp = (uint32_t*)(smraw + O_KEYP);

    const int tid    = threadIdx.x;
    const int lane   = tid & 31;
    const int wid    = tid >> 5;
    const int warp_m = wid >> 2;   // 0..1
    const int warp_n = wid & 3;    // 0..3
    const int NT     = (Brows + TROWS - 1) / TROWS;
    const int stride = gridDim.x;

    const int rowloc = (wid << 3) + (lane & 7);   // 0..63
    const int g      = lane >> 3;                 // 0..3

    if (tid < 128) rad[tid] = radg[tid];

    // prologue: c -> B hi plane (+csq, rows rowloc and rowloc+64); x tile0 -> A hi (+xsq)
    {
        float4 vb[8];
        load_row_quads(vb, cg, (long long)rowloc, g);
        cvt_hi(sb, B_HI, rowloc, g, vb, csq);
        load_row_quads(vb, cg, (long long)(rowloc + 64), g);
        cvt_hi(sb, B_HI, rowloc + 64, g, vb, csq);
        long long rowg = (long long)blockIdx.x * TROWS + rowloc;
        if (rowg >= Brows) rowg = Brows - 1;
        float4 va[8];
        load_row_quads(va, xg, rowg, g);
        cvt_hi(sb, A_HI, rowloc, g, va, xsq);
    }
    __syncthreads();

    float csr[8];
#pragma unroll
    for (int nt = 0; nt < 4; nt++)
#pragma unroll
        for (int e = 0; e < 2; e++)
            csr[nt * 2 + e] = csq[warp_n * 32 + nt * 8 + (lane & 3) * 2 + e];

    const uint32_t arow = (uint32_t)(warp_m * 32 + (lane & 15));
    const uint32_t akh  = (uint32_t)(lane >> 4);
    const uint32_t bn4  = (uint32_t)(warp_n * 32 + ((lane >> 4) << 3) + (lane & 7));
    const uint32_t bkh  = (uint32_t)((lane >> 3) & 1);

    for (int t = blockIdx.x; t < NT; t += stride) {
        const long long row0 = (long long)t * TROWS;

        // ---- MMA mainloop: warp tile 32x32, single hh pass ----
        float acc[2][4][4];
#pragma unroll
        for (int a = 0; a < 2; a++)
#pragma unroll
            for (int bq = 0; bq < 4; bq++)
#pragma unroll
                for (int e = 0; e < 4; e++) acc[a][bq][e] = 0.f;

#pragma unroll
        for (int ch = 0; ch < 8; ch++) {
            uint32_t ah[2][4];
            const uint32_t akc = (uint32_t)ch * 2 + akh;
#pragma unroll
            for (int mt = 0; mt < 2; mt++)
                ldm_x4(ah[mt], sb + A_HI + bswz(arow + (uint32_t)mt * 16, akc));
            uint32_t bh[4][2];
            const uint32_t bkc = (uint32_t)ch * 2 + bkh;
#pragma unroll
            for (int n2 = 0; n2 < 2; n2++) {
                uint32_t fh[4];
                ldm_x4(fh, sb + B_HI + bswz(bn4 + (uint32_t)n2 * 16, bkc));
                bh[2 * n2][0] = fh[0]; bh[2 * n2][1] = fh[1];
                bh[2 * n2 + 1][0] = fh[2]; bh[2 * n2 + 1][1] = fh[3];
            }
#pragma unroll
            for (int mt = 0; mt < 2; mt++)
#pragma unroll
                for (int nt = 0; nt < 4; nt++)
                    mma16816(acc[mt][nt], ah[mt], bh[nt]);
        }

        // ---- per-row top-2 over this warp's 32 cols (u32 packed keys) ----
#pragma unroll
        for (int mt = 0; mt < 2; mt++) {
#pragma unroll
            for (int s = 0; s < 2; s++) {
                uint32_t k1 = ~0u, k2 = ~0u;
#pragma unroll
                for (int nt = 0; nt < 4; nt++) {
#pragma unroll
                    for (int e = 0; e < 2; e++) {
                        int col = warp_n * 32 + nt * 8 + (lane & 3) * 2 + e;
                        float sc = fmaf(-2.f, acc[mt][nt][s * 2 + e], csr[nt * 2 + e]);
                        uint32_t kk = (f2ord(sc) & 0xFFFFFF80u) | (uint32_t)col;
                        if (kk < k1) { k2 = k1; k1 = kk; }
                        else if (kk < k2) k2 = kk;
                    }
                }
#pragma unroll
                for (int m = 1; m < 4; m <<= 1) {
                    uint32_t o1 = __shfl_xor_sync(0xffffffffu, k1, m);
                    uint32_t o2 = __shfl_xor_sync(0xffffffffu, k2, m);
                    if (o1 < k1) { k2 = (k1 < o2) ? k1 : o2; k1 = o1; }
                    else         { k2 = (k2 < o1) ? k2 : o1; }
                }
                if ((lane & 3) == 0) {
                    int rloc = warp_m * 32 + mt * 16 + (lane >> 2) + s * 8;
                    keyp[rloc * 8 + warp_n * 2 + 0] = k1;
                    keyp[rloc * 8 + warp_n * 2 + 1] = k2;
                }
            }
        }
        __syncthreads();

        // ---- prefetch next tile's x (flight hides under merge) ----
        int tn = t + stride;
        bool hn = (tn < NT);
        float4 v[8];
        if (hn) {
            long long rowg = (long long)tn * TROWS + rowloc;
            if (rowg >= Brows) rowg = Brows - 1;
            load_row_quads(v, xg, rowg, g);
        }

        // ---- merge; refine near-ties; emit idx + strength ----
        if (tid < TROWS) {
            uint32_t g1 = ~0u, g2 = ~0u;
#pragma unroll
            for (int w = 0; w < 4; w++) {
                uint32_t o1 = keyp[tid * 8 + w * 2 + 0];
                uint32_t o2 = keyp[tid * 8 + w * 2 + 1];
                if (o1 < g1) { g2 = (g1 < o2) ? g1 : o2; g1 = o1; }
                else         { g2 = (g2 < o1) ? g2 : o1; }
            }
            int j = (int)(g1 & 127u);
            long long rowg = row0 + tid;
            if (rowg < Brows) {
                float s1 = ord2f(g1 & 0xFFFFFF80u);
                float s2 = ord2f(g2 & 0xFFFFFF80u);
                float d2;
                if (s2 - s1 < REFINE_T) {
                    const float4* xp4 = reinterpret_cast<const float4*>(xg + rowg * EDIM);
                    int jb = (int)(g2 & 127u);
                    float d2a = exact_d2(xp4, reinterpret_cast<const float4*>(cg + (long long)j * EDIM));
                    float d2b = exact_d2(xp4, reinterpret_cast<const float4*>(cg + (long long)jb * EDIM));
                    if (d2b < d2a || (d2b == d2a && jb < j)) { j = jb; d2a = d2b; }
                    d2 = d2a;
                } else {
                    d2 = xsq[tid] + s1;
                }
                float dist = sqrtf(fmaxf(d2, 0.f));
                float strength = expf(-dist / (rad[j] + 1e-8f));
                g_s[rowg] = 0.1f * strength;
                g_j[rowg] = j;
                if (write_idx)
                    out[(long long)Brows * EDIM + rowg] = (float)j;
            }
        }
        __syncthreads();

        if (hn) cvt_hi(sb, A_HI, rowloc, g, v, xsq);
        __syncthreads();
    }
}

// ============================ kernel 2: blend =============================
__global__ void __launch_bounds__(256)
blend_kernel(const float* __restrict__ xg, const float* __restrict__ cg,
             float* __restrict__ out, int Brows)
{
    const float4* x4 = reinterpret_cast<const float4*>(xg);
    const float4* c4 = reinterpret_cast<const float4*>(cg);
    float4* o4 = reinterpret_cast<float4*>(out);
    const long long total = (long long)Brows * 32;
    const long long step = (long long)gridDim.x * blockDim.x;
    for (long long f = (long long)blockIdx.x * blockDim.x + threadIdx.x; f < total; f += step) {
        long long row = f >> 5;
        int q = (int)(f & 31);
        int j = g_j[row];          // uniform across warp -> broadcast
        float s = g_s[row];
        float om = 1.f - s;
        float4 xv = __ldg(x4 + row * 32 + q);
        float4 cv = __ldg(c4 + (long long)j * 32 + q);
        float4 o;
        o.x = fmaf(cv.x, s, xv.x * om);
        o.y = fmaf(cv.y, s, xv.y * om);
        o.z = fmaf(cv.z, s, xv.z * om);
        o.w = fmaf(cv.w, s, xv.w * om);
        o4[row * 32 + q] = o;
    }
}

extern "C" void kernel_launch(void* const* d_in, const int* in_sizes, int n_in,
                              void* d_out, int out_size)
{
    const float* x     = (const float*)d_in[0];
    const float* c     = (const float*)d_in[1];
    const float* radii = (const float*)d_in[2];
    float* out = (float*)d_out;

    int Brows = in_sizes[0] / EDIM;
    if (Brows > BMAX) Brows = BMAX;
    int write_idx = (out_size >= Brows * (EDIM + 1)) ? 1 : 0;

    int sms = 148;
    cudaDeviceGetAttribute(&sms, cudaDevAttrMultiProcessorCount, 0);
    int nt = (Brows + TROWS - 1) / TROWS;
    int grid1 = 3 * sms < nt ? 3 * sms : nt;

    cudaFuncSetAttribute(argmin_kernel,
                         cudaFuncAttributeMaxDynamicSharedMemorySize, (int)SMEM_K1);
    argmin_kernel<<<grid1, NTH, SMEM_K1>>>(x, c, radii, out, Brows, write_idx);

    int grid2 = sms * 8;
    blend_kernel<<<grid2, 256>>>(x, c, out, Brows);
}

// round 12
// speedup vs baseline: 1.1203x; 1.1203x over previous
#include <cuda_runtime.h>
#include <cuda_fp16.h>
#include <cstdint>
#include <math.h>

#define EDIM 128
#define NTH  256
#define TROWS 64   // rows per CTA tile (kernel 1)
#define BMAX 524288

// ---- kernel-1 dynamic smem byte offsets ----
#define B_HI    0u        // c hi plane [n=128][k=128] fp16 swizzled (32 KB)
#define A_HI    32768u    // x hi plane [m=64][k=128] fp16 (16 KB)
#define O_CSQ   49152u    // float[128]
#define O_RAD   49664u    // float[128]
#define O_XSQ   50176u    // float[64]
#define O_KEYP  50432u    // u32[64][8] = 2048
#define SMEM_K1 52480u

#define REFINE_T 2.5e-2f

// scratch for strength + index between the two kernels
__device__ float g_s[BMAX];
__device__ int   g_j[BMAX];

__device__ __forceinline__ uint32_t smem_u32(const void* p) {
    uint32_t a;
    asm("{ .reg .u64 t; cvta.to.shared.u64 t, %1; cvt.u32.u64 %0, t; }" : "=r"(a) : "l"(p));
    return a;
}
__device__ __forceinline__ uint32_t bswz(uint32_t n, uint32_t kc) {
    return n * 256u + ((((kc ^ n) & 7u) | (kc & 8u)) << 4);
}
__device__ __forceinline__ uint32_t pack_h2(float lo, float hi) {
    uint32_t r;
    asm("cvt.rn.f16x2.f32 %0, %1, %2;" : "=r"(r) : "f"(hi), "f"(lo));
    return r;
}
__device__ __forceinline__ void ldm_x4(uint32_t* r, uint32_t addr) {
    asm volatile("ldmatrix.sync.aligned.m8n8.x4.shared.b16 {%0,%1,%2,%3}, [%4];"
                 : "=r"(r[0]), "=r"(r[1]), "=r"(r[2]), "=r"(r[3]) : "r"(addr));
}
__device__ __forceinline__ void mma16816(float* d, const uint32_t* a, const uint32_t* b) {
    asm volatile("mma.sync.aligned.m16n8k16.row.col.f32.f16.f16.f32 "
                 "{%0,%1,%2,%3}, {%4,%5,%6,%7}, {%8,%9}, {%0,%1,%2,%3};"
                 : "+f"(d[0]), "+f"(d[1]), "+f"(d[2]), "+f"(d[3])
                 : "r"(a[0]), "r"(a[1]), "r"(a[2]), "r"(a[3]), "r"(b[0]), "r"(b[1]));
}
#define STS64A(addr, a, b) \
    asm volatile("st.shared.v2.b32 [%0], {%1,%2};" :: "r"(addr), "r"(a), "r"(b) : "memory")

__device__ __forceinline__ uint32_t f2ord(float f) {
    uint32_t u = __float_as_uint(f);
    return (u & 0x80000000u) ? ~u : (u | 0x80000000u);
}
__device__ __forceinline__ float ord2f(uint32_t o) {
    uint32_t u = (o & 0x80000000u) ? (o ^ 0x80000000u) : ~o;
    return __uint_as_float(u);
}
__device__ __forceinline__ float exact_d2(const float4* __restrict__ xp,
                                          const float4* __restrict__ cp) {
    float a0 = 0.f, a1 = 0.f;
#pragma unroll 8
    for (int q = 0; q < 32; q++) {
        float4 xv = __ldg(xp + q), cv = __ldg(cp + q);
        float t0 = xv.x - cv.x, t1 = xv.y - cv.y;
        float t2 = xv.z - cv.z, t3 = xv.w - cv.w;
        a0 = fmaf(t0, t0, a0); a1 = fmaf(t1, t1, a1);
        a0 = fmaf(t2, t2, a0); a1 = fmaf(t3, t3, a1);
    }
    return a0 + a1;
}
__device__ __forceinline__ void load_row_quads(float4* v, const float* __restrict__ base,
                                               long long row, int g) {
    const float4* gp = reinterpret_cast<const float4*>(base + row * EDIM) + g;
#pragma unroll
    for (int i = 0; i < 8; i++) v[i] = __ldg(gp + 4 * i);
}
// convert 8 float4s of a row -> fp16 hi plane; exact f32 row-sum to sqout
__device__ __forceinline__ void cvt_hi(uint32_t sb, uint32_t plane, int rowloc, int g,
                                       const float4* v, float* sqout) {
    float acc = 0.f;
#pragma unroll
    for (int i = 0; i < 8; i++) {
        float4 f = v[i];
        int c4 = g + 4 * i;
        uint32_t kc = (uint32_t)(c4 >> 1), hf = (uint32_t)(c4 & 1) * 8u;
        uint32_t h0 = pack_h2(f.x, f.y), h1 = pack_h2(f.z, f.w);
        acc = fmaf(f.x, f.x, acc); acc = fmaf(f.y, f.y, acc);
        acc = fmaf(f.z, f.z, acc); acc = fmaf(f.w, f.w, acc);
        STS64A(sb + plane + bswz((uint32_t)rowloc, kc) + hf, h0, h1);
    }
    acc += __shfl_xor_sync(0xffffffffu, acc, 8);
    acc += __shfl_xor_sync(0xffffffffu, acc, 16);
    if (g == 0) sqout[rowloc] = acc;
}

// ============================ kernel 1: argmin ============================
__global__ void __launch_bounds__(NTH, 2)
argmin_kernel(const float* __restrict__ xg, const float* __restrict__ cg,
              const float* __restrict__ radg, float* __restrict__ out,
              int Brows, int write_idx)
{
    extern __shared__ char smraw[];
    const uint32_t sb = smem_u32(smraw);
    float* csq  = (float*)(smraw + O_CSQ);
    float* rad  = (float*)(smraw + O_RAD);
    float* xsq  = (float*)(smraw + O_XSQ);
    uint32_t* keyp = (uint32_t*)(smraw + O_KEYP);

    const int tid    = threadIdx.x;
    const int lane   = tid & 31;
    const int wid    = tid >> 5;
    const int warp_m = wid >> 2;   // 0..1
    const int warp_n = wid & 3;    // 0..3
    const int NT     = (Brows + TROWS - 1) / TROWS;
    const int stride = gridDim.x;

    const int rowloc = (wid << 3) + (lane & 7);   // 0..63
    const int g      = lane >> 3;                 // 0..3

    if (tid < 128) rad[tid] = radg[tid];

    // prologue: c -> B hi plane (+csq); x tile0 -> A hi (+xsq)
    {
        float4 vb[8];
        load_row_quads(vb, cg, (long long)rowloc, g);
        cvt_hi(sb, B_HI, rowloc, g, vb, csq);
        load_row_quads(vb, cg, (long long)(rowloc + 64), g);
        cvt_hi(sb, B_HI, rowloc + 64, g, vb, csq);
        long long rowg = (long long)blockIdx.x * TROWS + rowloc;
        if (rowg >= Brows) rowg = Brows - 1;
        float4 va[8];
        load_row_quads(va, xg, rowg, g);
        cvt_hi(sb, A_HI, rowloc, g, va, xsq);
    }
    __syncthreads();

    float csr[8];
#pragma unroll
    for (int nt = 0; nt < 4; nt++)
#pragma unroll
        for (int e = 0; e < 2; e++)
            csr[nt * 2 + e] = csq[warp_n * 32 + nt * 8 + (lane & 3) * 2 + e];

    const uint32_t arow = (uint32_t)(warp_m * 32 + (lane & 15));
    const uint32_t akh  = (uint32_t)(lane >> 4);
    const uint32_t bn4  = (uint32_t)(warp_n * 32 + ((lane >> 4) << 3) + (lane & 7));
    const uint32_t bkh  = (uint32_t)((lane >> 3) & 1);

    for (int t = blockIdx.x; t < NT; t += stride) {
        const long long row0 = (long long)t * TROWS;

        // ---- MMA mainloop: warp tile 32x32, single hh pass ----
        float acc[2][4][4];
#pragma unroll
        for (int a = 0; a < 2; a++)
#pragma unroll
            for (int bq = 0; bq < 4; bq++)
#pragma unroll
                for (int e = 0; e < 4; e++) acc[a][bq][e] = 0.f;

#pragma unroll
        for (int ch = 0; ch < 8; ch++) {
            uint32_t ah[2][4];
            const uint32_t akc = (uint32_t)ch * 2 + akh;
#pragma unroll
            for (int mt = 0; mt < 2; mt++)
                ldm_x4(ah[mt], sb + A_HI + bswz(arow + (uint32_t)mt * 16, akc));
            uint32_t bh[4][2];
            const uint32_t bkc = (uint32_t)ch * 2 + bkh;
#pragma unroll
            for (int n2 = 0; n2 < 2; n2++) {
                uint32_t fh[4];
                ldm_x4(fh, sb + B_HI + bswz(bn4 + (uint32_t)n2 * 16, bkc));
                bh[2 * n2][0] = fh[0]; bh[2 * n2][1] = fh[1];
                bh[2 * n2 + 1][0] = fh[2]; bh[2 * n2 + 1][1] = fh[3];
            }
#pragma unroll
            for (int mt = 0; mt < 2; mt++)
#pragma unroll
                for (int nt = 0; nt < 4; nt++)
                    mma16816(acc[mt][nt], ah[mt], bh[nt]);
        }

        // ---- per-row top-2 over this warp's 32 cols (u32 packed keys) ----
#pragma unroll
        for (int mt = 0; mt < 2; mt++) {
#pragma unroll
            for (int s = 0; s < 2; s++) {
                uint32_t k1 = ~0u, k2 = ~0u;
#pragma unroll
                for (int nt = 0; nt < 4; nt++) {
#pragma unroll
                    for (int e = 0; e < 2; e++) {
                        int col = warp_n * 32 + nt * 8 + (lane & 3) * 2 + e;
                        float sc = fmaf(-2.f, acc[mt][nt][s * 2 + e], csr[nt * 2 + e]);
                        uint32_t kk = (f2ord(sc) & 0xFFFFFF80u) | (uint32_t)col;
                        if (kk < k1) { k2 = k1; k1 = kk; }
                        else if (kk < k2) k2 = kk;
                    }
                }
#pragma unroll
                for (int m = 1; m < 4; m <<= 1) {
                    uint32_t o1 = __shfl_xor_sync(0xffffffffu, k1, m);
                    uint32_t o2 = __shfl_xor_sync(0xffffffffu, k2, m);
                    if (o1 < k1) { k2 = (k1 < o2) ? k1 : o2; k1 = o1; }
                    else         { k2 = (k2 < o1) ? k2 : o1; }
                }
                if ((lane & 3) == 0) {
                    int rloc = warp_m * 32 + mt * 16 + (lane >> 2) + s * 8;
                    keyp[rloc * 8 + warp_n * 2 + 0] = k1;
                    keyp[rloc * 8 + warp_n * 2 + 1] = k2;
                }
            }
        }
        __syncthreads();

        // ---- prefetch next tile's x (flight hides under merge) ----
        int tn = t + stride;
        bool hn = (tn < NT);
        float4 v[8];
        if (hn) {
            long long rowg = (long long)tn * TROWS + rowloc;
            if (rowg >= Brows) rowg = Brows - 1;
            load_row_quads(v, xg, rowg, g);
        }

        // ---- merge; refine near-ties; emit idx + strength ----
        if (tid < TROWS) {
            uint32_t g1 = ~0u, g2 = ~0u;
#pragma unroll
            for (int w = 0; w < 4; w++) {
                uint32_t o1 = keyp[tid * 8 + w * 2 + 0];
                uint32_t o2 = keyp[tid * 8 + w * 2 + 1];
                if (o1 < g1) { g2 = (g1 < o2) ? g1 : o2; g1 = o1; }
                else         { g2 = (g2 < o1) ? g2 : o1; }
            }
            int j = (int)(g1 & 127u);
            long long rowg = row0 + tid;
            if (rowg < Brows) {
                float s1 = ord2f(g1 & 0xFFFFFF80u);
                float s2 = ord2f(g2 & 0xFFFFFF80u);
                float d2;
                if (s2 - s1 < REFINE_T) {
                    const float4* xp4 = reinterpret_cast<const float4*>(xg + rowg * EDIM);
                    int jb = (int)(g2 & 127u);
                    float d2a = exact_d2(xp4, reinterpret_cast<const float4*>(cg + (long long)j * EDIM));
                    float d2b = exact_d2(xp4, reinterpret_cast<const float4*>(cg + (long long)jb * EDIM));
                    if (d2b < d2a || (d2b == d2a && jb < j)) { j = jb; d2a = d2b; }
                    d2 = d2a;
                } else {
                    d2 = xsq[tid] + s1;
                }
                float dist = sqrtf(fmaxf(d2, 0.f));
                float strength = expf(-dist / (rad[j] + 1e-8f));
                g_s[rowg] = 0.1f * strength;
                g_j[rowg] = j;
                if (write_idx)
                    out[(long long)Brows * EDIM + rowg] = (float)j;
            }
        }
        __syncthreads();

        if (hn) cvt_hi(sb, A_HI, rowloc, g, v, xsq);
        __syncthreads();
    }
}

// ============================ kernel 2: blend =============================
__global__ void __launch_bounds__(256)
blend_kernel(const float* __restrict__ xg, const float* __restrict__ cg,
             float* __restrict__ out, int Brows)
{
    const float4* x4 = reinterpret_cast<const float4*>(xg);
    const float4* c4 = reinterpret_cast<const float4*>(cg);
    float4* o4 = reinterpret_cast<float4*>(out);
    const long long total = (long long)Brows * 32;
    const long long step = (long long)gridDim.x * blockDim.x;
    for (long long f = (long long)blockIdx.x * blockDim.x + threadIdx.x; f < total; f += step) {
        long long row = f >> 5;
        int q = (int)(f & 31);
        int j = g_j[row];          // uniform across warp -> broadcast
        float s = g_s[row];
        float om = 1.f - s;
        float4 xv = __ldg(x4 + row * 32 + q);
        float4 cv = __ldg(c4 + (long long)j * 32 + q);
        float4 o;
        o.x = fmaf(cv.x, s, xv.x * om);
        o.y = fmaf(cv.y, s, xv.y * om);
        o.z = fmaf(cv.z, s, xv.z * om);
        o.w = fmaf(cv.w, s, xv.w * om);
        o4[row * 32 + q] = o;
    }
}

extern "C" void kernel_launch(void* const* d_in, const int* in_sizes, int n_in,
                              void* d_out, int out_size)
{
    const float* x     = (const float*)d_in[0];
    const float* c     = (const float*)d_in[1];
    const float* radii = (const float*)d_in[2];
    float* out = (float*)d_out;

    int Brows = in_sizes[0] / EDIM;
    if (Brows > BMAX) Brows = BMAX;
    int write_idx = (out_size >= Brows * (EDIM + 1)) ? 1 : 0;

    int sms = 148;
    cudaDeviceGetAttribute(&sms, cudaDevAttrMultiProcessorCount, 0);
    int nt = (Brows + TROWS - 1) / TROWS;
    int grid1 = 2 * sms < nt ? 2 * sms : nt;

    cudaFuncSetAttribute(argmin_kernel,
                         cudaFuncAttributeMaxDynamicSharedMemorySize, (int)SMEM_K1);
    argmin_kernel<<<grid1, NTH, SMEM_K1>>>(x, c, radii, out, Brows, write_idx);

    int grid2 = sms * 8;
    blend_kernel<<<grid2, 256>>>(x, c, out, Brows);
}

// round 13
// speedup vs baseline: 1.1600x; 1.0354x over previous
#include <cuda_runtime.h>
#include <cuda_fp16.h>
#include <cstdint>
#include <math.h>

#define EDIM 128
#define NTH  256
#define TROWS 128  // rows per CTA tile (kernel 1)
#define BMAX 524288

// ---- kernel-1 dynamic smem byte offsets ----
#define B_HI    0u        // c hi plane [n=128][k=128] fp16 swizzled (32 KB)
#define A_HI    32768u    // x hi plane [m=128][k=128] fp16 (32 KB)
#define O_CSQ   65536u    // float[128]
#define O_RAD   66048u    // float[128]
#define O_XSQ   66560u    // float[128]
#define O_KEYP  67072u    // u32[128][8] = 4096
#define SMEM_K1 71168u

#define REFINE_T 2.5e-2f

// scratch for strength + index between the two kernels
__device__ float g_s[BMAX];
__device__ int   g_j[BMAX];

__device__ __forceinline__ uint32_t smem_u32(const void* p) {
    uint32_t a;
    asm("{ .reg .u64 t; cvta.to.shared.u64 t, %1; cvt.u32.u64 %0, t; }" : "=r"(a) : "l"(p));
    return a;
}
__device__ __forceinline__ uint32_t bswz(uint32_t n, uint32_t kc) {
    return n * 256u + ((((kc ^ n) & 7u) | (kc & 8u)) << 4);
}
__device__ __forceinline__ uint32_t pack_h2(float lo, float hi) {
    uint32_t r;
    asm("cvt.rn.f16x2.f32 %0, %1, %2;" : "=r"(r) : "f"(hi), "f"(lo));
    return r;
}
__device__ __forceinline__ void ldm_x4(uint32_t* r, uint32_t addr) {
    asm volatile("ldmatrix.sync.aligned.m8n8.x4.shared.b16 {%0,%1,%2,%3}, [%4];"
                 : "=r"(r[0]), "=r"(r[1]), "=r"(r[2]), "=r"(r[3]) : "r"(addr));
}
__device__ __forceinline__ void mma16816(float* d, const uint32_t* a, const uint32_t* b) {
    asm volatile("mma.sync.aligned.m16n8k16.row.col.f32.f16.f16.f32 "
                 "{%0,%1,%2,%3}, {%4,%5,%6,%7}, {%8,%9}, {%0,%1,%2,%3};"
                 : "+f"(d[0]), "+f"(d[1]), "+f"(d[2]), "+f"(d[3])
                 : "r"(a[0]), "r"(a[1]), "r"(a[2]), "r"(a[3]), "r"(b[0]), "r"(b[1]));
}
#define STS64A(addr, a, b) \
    asm volatile("st.shared.v2.b32 [%0], {%1,%2};" :: "r"(addr), "r"(a), "r"(b) : "memory")

__device__ __forceinline__ uint32_t f2ord(float f) {
    uint32_t u = __float_as_uint(f);
    return (u & 0x80000000u) ? ~u : (u | 0x80000000u);
}
__device__ __forceinline__ float ord2f(uint32_t o) {
    uint32_t u = (o & 0x80000000u) ? (o ^ 0x80000000u) : ~o;
    return __uint_as_float(u);
}
__device__ __forceinline__ float exact_d2(const float4* __restrict__ xp,
                                          const float4* __restrict__ cp) {
    float a0 = 0.f, a1 = 0.f;
#pragma unroll 8
    for (int q = 0; q < 32; q++) {
        float4 xv = __ldg(xp + q), cv = __ldg(cp + q);
        float t0 = xv.x - cv.x, t1 = xv.y - cv.y;
        float t2 = xv.z - cv.z, t3 = xv.w - cv.w;
        a0 = fmaf(t0, t0, a0); a1 = fmaf(t1, t1, a1);
        a0 = fmaf(t2, t2, a0); a1 = fmaf(t3, t3, a1);
    }
    return a0 + a1;
}
__device__ __forceinline__ void load_row_quads(float4* v, const float* __restrict__ base,
                                               long long row, int g) {
    const float4* gp = reinterpret_cast<const float4*>(base + row * EDIM) + g;
#pragma unroll
    for (int i = 0; i < 8; i++) v[i] = __ldg(gp + 4 * i);
}
// convert 8 float4s of a row -> fp16 hi plane; exact f32 row-sum to sqout
__device__ __forceinline__ void cvt_hi(uint32_t sb, uint32_t plane, int rowloc, int g,
                                       const float4* v, float* sqout) {
    float acc = 0.f;
#pragma unroll
    for (int i = 0; i < 8; i++) {
        float4 f = v[i];
        int c4 = g + 4 * i;
        uint32_t kc = (uint32_t)(c4 >> 1), hf = (uint32_t)(c4 & 1) * 8u;
        uint32_t h0 = pack_h2(f.x, f.y), h1 = pack_h2(f.z, f.w);
        acc = fmaf(f.x, f.x, acc); acc = fmaf(f.y, f.y, acc);
        acc = fmaf(f.z, f.z, acc); acc = fmaf(f.w, f.w, acc);
        STS64A(sb + plane + bswz((uint32_t)rowloc, kc) + hf, h0, h1);
    }
    acc += __shfl_xor_sync(0xffffffffu, acc, 8);
    acc += __shfl_xor_sync(0xffffffffu, acc, 16);
    if (g == 0) sqout[rowloc] = acc;
}

// ============================ kernel 1: argmin ============================
__global__ void __launch_bounds__(NTH, 2)
argmin_kernel(const float* __restrict__ xg, const float* __restrict__ cg,
              const float* __restrict__ radg, float* __restrict__ out,
              int Brows, int write_idx)
{
    extern __shared__ char smraw[];
    const uint32_t sb = smem_u32(smraw);
    float* csq  = (float*)(smraw + O_CSQ);
    float* rad  = (float*)(smraw + O_RAD);
    float* xsq  = (float*)(smraw + O_XSQ);
    uint32_t* keyp = (uint32_t*)(smraw + O_KEYP);

    const int tid    = threadIdx.x;
    const int lane   = tid & 31;
    const int wid    = tid >> 5;
    const int warp_m = wid >> 2;   // 0..1 -> rows warp_m*64
    const int warp_n = wid & 3;    // 0..3 -> cols warp_n*32
    const int NT     = (Brows + TROWS - 1) / TROWS;
    const int stride = gridDim.x;

    const int rowloc = (wid << 3) + (lane & 7);   // 0..63 (convert half-pass row)
    const int g      = lane >> 3;                 // 0..3

    if (tid < 128) rad[tid] = radg[tid];

    // prologue: c -> B hi plane (+csq); x tile0 (128 rows) -> A hi (+xsq)
    {
        float4 vb[8];
        load_row_quads(vb, cg, (long long)rowloc, g);
        cvt_hi(sb, B_HI, rowloc, g, vb, csq);
        load_row_quads(vb, cg, (long long)(rowloc + 64), g);
        cvt_hi(sb, B_HI, rowloc + 64, g, vb, csq);
        long long base = (long long)blockIdx.x * TROWS;
        long long r0c = base + rowloc;      if (r0c >= Brows) r0c = Brows - 1;
        long long r1c = base + rowloc + 64; if (r1c >= Brows) r1c = Brows - 1;
        float4 va[8];
        load_row_quads(va, xg, r0c, g);
        cvt_hi(sb, A_HI, rowloc, g, va, xsq);
        load_row_quads(va, xg, r1c, g);
        cvt_hi(sb, A_HI, rowloc + 64, g, va, xsq);
    }
    __syncthreads();

    float csr[8];
#pragma unroll
    for (int nt = 0; nt < 4; nt++)
#pragma unroll
        for (int e = 0; e < 2; e++)
            csr[nt * 2 + e] = csq[warp_n * 32 + nt * 8 + (lane & 3) * 2 + e];

    const uint32_t arow = (uint32_t)(warp_m * 64 + (lane & 15));
    const uint32_t akh  = (uint32_t)(lane >> 4);
    const uint32_t bn4  = (uint32_t)(warp_n * 32 + ((lane >> 4) << 3) + (lane & 7));
    const uint32_t bkh  = (uint32_t)((lane >> 3) & 1);

    for (int t = blockIdx.x; t < NT; t += stride) {
        const long long row0 = (long long)t * TROWS;

        // ---- MMA mainloop: warp tile 64x32, single hh pass ----
        float acc[4][4][4];
#pragma unroll
        for (int a = 0; a < 4; a++)
#pragma unroll
            for (int bq = 0; bq < 4; bq++)
#pragma unroll
                for (int e = 0; e < 4; e++) acc[a][bq][e] = 0.f;

#pragma unroll
        for (int ch = 0; ch < 8; ch++) {
            uint32_t ah[4][4];
            const uint32_t akc = (uint32_t)ch * 2 + akh;
#pragma unroll
            for (int mt = 0; mt < 4; mt++)
                ldm_x4(ah[mt], sb + A_HI + bswz(arow + (uint32_t)mt * 16, akc));
            uint32_t bh[4][2];
            const uint32_t bkc = (uint32_t)ch * 2 + bkh;
#pragma unroll
            for (int n2 = 0; n2 < 2; n2++) {
                uint32_t fh[4];
                ldm_x4(fh, sb + B_HI + bswz(bn4 + (uint32_t)n2 * 16, bkc));
                bh[2 * n2][0] = fh[0]; bh[2 * n2][1] = fh[1];
                bh[2 * n2 + 1][0] = fh[2]; bh[2 * n2 + 1][1] = fh[3];
            }
#pragma unroll
            for (int mt = 0; mt < 4; mt++)
#pragma unroll
                for (int nt = 0; nt < 4; nt++)
                    mma16816(acc[mt][nt], ah[mt], bh[nt]);
        }

        // ---- per-row top-2 over this warp's 32 cols (u32 packed keys) ----
#pragma unroll
        for (int mt = 0; mt < 4; mt++) {
#pragma unroll
            for (int s = 0; s < 2; s++) {
                uint32_t k1 = ~0u, k2 = ~0u;
#pragma unroll
                for (int nt = 0; nt < 4; nt++) {
#pragma unroll
                    for (int e = 0; e < 2; e++) {
                        int col = warp_n * 32 + nt * 8 + (lane & 3) * 2 + e;
                        float sc = fmaf(-2.f, acc[mt][nt][s * 2 + e], csr[nt * 2 + e]);
                        uint32_t kk = (f2ord(sc) & 0xFFFFFF80u) | (uint32_t)col;
                        if (kk < k1) { k2 = k1; k1 = kk; }
                        else if (kk < k2) k2 = kk;
                    }
                }
#pragma unroll
                for (int m = 1; m < 4; m <<= 1) {
                    uint32_t o1 = __shfl_xor_sync(0xffffffffu, k1, m);
                    uint32_t o2 = __shfl_xor_sync(0xffffffffu, k2, m);
                    if (o1 < k1) { k2 = (k1 < o2) ? k1 : o2; k1 = o1; }
                    else         { k2 = (k2 < o1) ? k2 : o1; }
                }
                if ((lane & 3) == 0) {
                    int rloc = warp_m * 64 + mt * 16 + (lane >> 2) + s * 8;
                    keyp[rloc * 8 + warp_n * 2 + 0] = k1;
                    keyp[rloc * 8 + warp_n * 2 + 1] = k2;
                }
            }
        }
        __syncthreads();

        // ---- prefetch first half of next tile's x (flight hides under merge) ----
        int tn = t + stride;
        bool hn = (tn < NT);
        float4 v[8];
        if (hn) {
            long long rowg = (long long)tn * TROWS + rowloc;
            if (rowg >= Brows) rowg = Brows - 1;
            load_row_quads(v, xg, rowg, g);
        }

        // ---- merge 4 warp-column results; refine near-ties; emit idx+strength ----
        if (tid < TROWS) {
            uint32_t g1 = ~0u, g2 = ~0u;
#pragma unroll
            for (int w = 0; w < 4; w++) {
                uint32_t o1 = keyp[tid * 8 + w * 2 + 0];
                uint32_t o2 = keyp[tid * 8 + w * 2 + 1];
                if (o1 < g1) { g2 = (g1 < o2) ? g1 : o2; g1 = o1; }
                else         { g2 = (g2 < o1) ? g2 : o1; }
            }
            int j = (int)(g1 & 127u);
            long long rowg = row0 + tid;
            if (rowg < Brows) {
                float s1 = ord2f(g1 & 0xFFFFFF80u);
                float s2 = ord2f(g2 & 0xFFFFFF80u);
                float d2;
                if (s2 - s1 < REFINE_T) {
                    const float4* xp4 = reinterpret_cast<const float4*>(xg + rowg * EDIM);
                    int jb = (int)(g2 & 127u);
                    float d2a = exact_d2(xp4, reinterpret_cast<const float4*>(cg + (long long)j * EDIM));
                    float d2b = exact_d2(xp4, reinterpret_cast<const float4*>(cg + (long long)jb * EDIM));
                    if (d2b < d2a || (d2b == d2a && jb < j)) { j = jb; d2a = d2b; }
                    d2 = d2a;
                } else {
                    d2 = xsq[tid] + s1;
                }
                float dist = sqrtf(fmaxf(d2, 0.f));
                float strength = expf(-dist / (rad[j] + 1e-8f));
                g_s[rowg] = 0.1f * strength;
                g_j[rowg] = j;
                if (write_idx)
                    out[(long long)Brows * EDIM + rowg] = (float)j;
            }
        }
        __syncthreads();

        // ---- convert next tile: half 0 from prefetched regs, half 1 fresh LDG ----
        if (hn) {
            long long base = (long long)tn * TROWS;
            long long r1c = base + rowloc + 64;
            if (r1c >= Brows) r1c = Brows - 1;
            float4 v2[8];
            load_row_quads(v2, xg, r1c, g);            // issue early; flight hides under cvt below
            cvt_hi(sb, A_HI, rowloc, g, v, xsq);
            cvt_hi(sb, A_HI, rowloc + 64, g, v2, xsq);
        }
        __syncthreads();
    }
}

// ============================ kernel 2: blend =============================
__global__ void __launch_bounds__(256)
blend_kernel(const float* __restrict__ xg, const float* __restrict__ cg,
             float* __restrict__ out, int Brows)
{
    const float4* x4 = reinterpret_cast<const float4*>(xg);
    const float4* c4 = reinterpret_cast<const float4*>(cg);
    float4* o4 = reinterpret_cast<float4*>(out);
    const long long total = (long long)Brows * 32;
    const long long step = (long long)gridDim.x * blockDim.x;
    for (long long f = (long long)blockIdx.x * blockDim.x + threadIdx.x; f < total; f += step) {
        long long row = f >> 5;
        int q = (int)(f & 31);
        int j = g_j[row];          // uniform across warp -> broadcast
        float s = g_s[row];
        float om = 1.f - s;
        float4 xv = __ldg(x4 + row * 32 + q);
        float4 cv = __ldg(c4 + (long long)j * 32 + q);
        float4 o;
        o.x = fmaf(cv.x, s, xv.x * om);
        o.y = fmaf(cv.y, s, xv.y * om);
        o.z = fmaf(cv.z, s, xv.z * om);
        o.w = fmaf(cv.w, s, xv.w * om);
        o4[row * 32 + q] = o;
    }
}

extern "C" void kernel_launch(void* const* d_in, const int* in_sizes, int n_in,
                              void* d_out, int out_size)
{
    const float* x     = (const float*)d_in[0];
    const float* c     = (const float*)d_in[1];
    const float* radii = (const float*)d_in[2];
    float* out = (float*)d_out;

    int Brows = in_sizes[0] / EDIM;
    if (Brows > BMAX) Brows = BMAX;
    int write_idx = (out_size >= Brows * (EDIM + 1)) ? 1 : 0;

    int sms = 148;
    cudaDeviceGetAttribute(&sms, cudaDevAttrMultiProcessorCount, 0);
    int nt = (Brows + TROWS - 1) / TROWS;
    int grid1 = 2 * sms < nt ? 2 * sms : nt;

    cudaFuncSetAttribute(argmin_kernel,
                         cudaFuncAttributeMaxDynamicSharedMemorySize, (int)SMEM_K1);
    argmin_kernel<<<grid1, NTH, SMEM_K1>>>(x, c, radii, out, Brows, write_idx);

    int grid2 = sms * 8;
    blend_kernel<<<grid2, 256>>>(x, c, out, Brows);
}

// round 14
// speedup vs baseline: 1.1821x; 1.0191x over previous
#include <cuda_runtime.h>
#include <cuda_fp16.h>
#include <cstdint>
#include <math.h>

#define EDIM 128
#define NTH  256
#define TROWS 128  // rows per CTA tile (kernel 1)
#define BMAX 524288

// ---- kernel-1 dynamic smem byte offsets ----
#define B_HI    0u        // c hi plane [n=128][k=128] fp16 swizzled (32 KB)
#define A_HI    32768u    // x hi plane [m=128][k=128] fp16 (32 KB)
#define O_CSQ   65536u    // float[128]
#define O_RAD   66048u    // float[128]
#define O_XSQ   66560u    // float[2][128] (double-buffered)
#define O_KEYP  67584u    // u32[128][8] = 4096
#define SMEM_K1 71680u

#define REFINE_T 2.5e-2f

// scratch for strength + index between the two kernels
__device__ float g_s[BMAX];
__device__ int   g_j[BMAX];

__device__ __forceinline__ uint32_t smem_u32(const void* p) {
    uint32_t a;
    asm("{ .reg .u64 t; cvta.to.shared.u64 t, %1; cvt.u32.u64 %0, t; }" : "=r"(a) : "l"(p));
    return a;
}
__device__ __forceinline__ uint32_t bswz(uint32_t n, uint32_t kc) {
    return n * 256u + ((((kc ^ n) & 7u) | (kc & 8u)) << 4);
}
__device__ __forceinline__ uint32_t pack_h2(float lo, float hi) {
    uint32_t r;
    asm("cvt.rn.f16x2.f32 %0, %1, %2;" : "=r"(r) : "f"(hi), "f"(lo));
    return r;
}
__device__ __forceinline__ void ldm_x4(uint32_t* r, uint32_t addr) {
    asm volatile("ldmatrix.sync.aligned.m8n8.x4.shared.b16 {%0,%1,%2,%3}, [%4];"
                 : "=r"(r[0]), "=r"(r[1]), "=r"(r[2]), "=r"(r[3]) : "r"(addr));
}
__device__ __forceinline__ void mma16816(float* d, const uint32_t* a, const uint32_t* b) {
    asm volatile("mma.sync.aligned.m16n8k16.row.col.f32.f16.f16.f32 "
                 "{%0,%1,%2,%3}, {%4,%5,%6,%7}, {%8,%9}, {%0,%1,%2,%3};"
                 : "+f"(d[0]), "+f"(d[1]), "+f"(d[2]), "+f"(d[3])
                 : "r"(a[0]), "r"(a[1]), "r"(a[2]), "r"(a[3]), "r"(b[0]), "r"(b[1]));
}
#define STS64A(addr, a, b) \
    asm volatile("st.shared.v2.b32 [%0], {%1,%2};" :: "r"(addr), "r"(a), "r"(b) : "memory")

__device__ __forceinline__ uint32_t f2ord(float f) {
    uint32_t u = __float_as_uint(f);
    return (u & 0x80000000u) ? ~u : (u | 0x80000000u);
}
__device__ __forceinline__ float ord2f(uint32_t o) {
    uint32_t u = (o & 0x80000000u) ? (o ^ 0x80000000u) : ~o;
    return __uint_as_float(u);
}
__device__ __forceinline__ uint32_t umin2(uint32_t a, uint32_t b) { return a < b ? a : b; }
__device__ __forceinline__ uint32_t umax2(uint32_t a, uint32_t b) { return a > b ? a : b; }

__device__ __forceinline__ float exact_d2(const float4* __restrict__ xp,
                                          const float4* __restrict__ cp) {
    float a0 = 0.f, a1 = 0.f;
#pragma unroll 8
    for (int q = 0; q < 32; q++) {
        float4 xv = __ldg(xp + q), cv = __ldg(cp + q);
        float t0 = xv.x - cv.x, t1 = xv.y - cv.y;
        float t2 = xv.z - cv.z, t3 = xv.w - cv.w;
        a0 = fmaf(t0, t0, a0); a1 = fmaf(t1, t1, a1);
        a0 = fmaf(t2, t2, a0); a1 = fmaf(t3, t3, a1);
    }
    return a0 + a1;
}
__device__ __forceinline__ void load_row_quads(float4* v, const float* __restrict__ base,
                                               long long row, int g) {
    const float4* gp = reinterpret_cast<const float4*>(base + row * EDIM) + g;
#pragma unroll
    for (int i = 0; i < 8; i++) v[i] = __ldg(gp + 4 * i);
}
// convert 8 float4s of a row -> fp16 hi plane; exact f32 row-sum to sqout
__device__ __forceinline__ void cvt_hi(uint32_t sb, uint32_t plane, int rowloc, int g,
                                       const float4* v, float* sqout) {
    float acc = 0.f;
#pragma unroll
    for (int i = 0; i < 8; i++) {
        float4 f = v[i];
        int c4 = g + 4 * i;
        uint32_t kc = (uint32_t)(c4 >> 1), hf = (uint32_t)(c4 & 1) * 8u;
        uint32_t h0 = pack_h2(f.x, f.y), h1 = pack_h2(f.z, f.w);
        acc = fmaf(f.x, f.x, acc); acc = fmaf(f.y, f.y, acc);
        acc = fmaf(f.z, f.z, acc); acc = fmaf(f.w, f.w, acc);
        STS64A(sb + plane + bswz((uint32_t)rowloc, kc) + hf, h0, h1);
    }
    acc += __shfl_xor_sync(0xffffffffu, acc, 8);
    acc += __shfl_xor_sync(0xffffffffu, acc, 16);
    if (g == 0) sqout[rowloc] = acc;
}

// ============================ kernel 1: argmin ============================
__global__ void __launch_bounds__(NTH, 2)
argmin_kernel(const float* __restrict__ xg, const float* __restrict__ cg,
              const float* __restrict__ radg, float* __restrict__ out,
              int Brows, int write_idx)
{
    extern __shared__ char smraw[];
    const uint32_t sb = smem_u32(smraw);
    float* csq  = (float*)(smraw + O_CSQ);
    float* rad  = (float*)(smraw + O_RAD);
    float* xsq  = (float*)(smraw + O_XSQ);   // [2][128]
    uint32_t* keyp = (uint32_t*)(smraw + O_KEYP);

    const int tid    = threadIdx.x;
    const int lane   = tid & 31;
    const int wid    = tid >> 5;
    const int warp_m = wid >> 2;   // 0..1 -> rows warp_m*64
    const int warp_n = wid & 3;    // 0..3 -> cols warp_n*32
    const int NT     = (Brows + TROWS - 1) / TROWS;
    const int stride = gridDim.x;

    const int rowloc = (wid << 3) + (lane & 7);   // 0..63 (convert half-pass row)
    const int g      = lane >> 3;                 // 0..3

    if (tid < 128) rad[tid] = radg[tid];

    // prologue: c -> B hi plane (+csq); x tile0 (128 rows) -> A hi (+xsq buf 0)
    {
        float4 vb[8];
        load_row_quads(vb, cg, (long long)rowloc, g);
        cvt_hi(sb, B_HI, rowloc, g, vb, csq);
        load_row_quads(vb, cg, (long long)(rowloc + 64), g);
        cvt_hi(sb, B_HI, rowloc + 64, g, vb, csq);
        long long base = (long long)blockIdx.x * TROWS;
        long long r0c = base + rowloc;      if (r0c >= Brows) r0c = Brows - 1;
        long long r1c = base + rowloc + 64; if (r1c >= Brows) r1c = Brows - 1;
        float4 va[8];
        load_row_quads(va, xg, r0c, g);
        cvt_hi(sb, A_HI, rowloc, g, va, xsq);
        load_row_quads(va, xg, r1c, g);
        cvt_hi(sb, A_HI, rowloc + 64, g, va, xsq);
    }
    __syncthreads();

    float csr[8];
#pragma unroll
    for (int nt = 0; nt < 4; nt++)
#pragma unroll
        for (int e = 0; e < 2; e++)
            csr[nt * 2 + e] = csq[warp_n * 32 + nt * 8 + (lane & 3) * 2 + e];

    const uint32_t arow = (uint32_t)(warp_m * 64 + (lane & 15));
    const uint32_t akh  = (uint32_t)(lane >> 4);
    const uint32_t bn4  = (uint32_t)(warp_n * 32 + ((lane >> 4) << 3) + (lane & 7));
    const uint32_t bkh  = (uint32_t)((lane >> 3) & 1);

    int xb = 0;   // xsq buffer parity for the current tile

    for (int t = blockIdx.x; t < NT; t += stride) {
        const long long row0 = (long long)t * TROWS;

        // ---- MMA mainloop: warp tile 64x32, single hh pass ----
        float acc[4][4][4];
#pragma unroll
        for (int a = 0; a < 4; a++)
#pragma unroll
            for (int bq = 0; bq < 4; bq++)
#pragma unroll
                for (int e = 0; e < 4; e++) acc[a][bq][e] = 0.f;

#pragma unroll
        for (int ch = 0; ch < 8; ch++) {
            uint32_t ah[4][4];
            const uint32_t akc = (uint32_t)ch * 2 + akh;
#pragma unroll
            for (int mt = 0; mt < 4; mt++)
                ldm_x4(ah[mt], sb + A_HI + bswz(arow + (uint32_t)mt * 16, akc));
            uint32_t bh[4][2];
            const uint32_t bkc = (uint32_t)ch * 2 + bkh;
#pragma unroll
            for (int n2 = 0; n2 < 2; n2++) {
                uint32_t fh[4];
                ldm_x4(fh, sb + B_HI + bswz(bn4 + (uint32_t)n2 * 16, bkc));
                bh[2 * n2][0] = fh[0]; bh[2 * n2][1] = fh[1];
                bh[2 * n2 + 1][0] = fh[2]; bh[2 * n2 + 1][1] = fh[3];
            }
#pragma unroll
            for (int mt = 0; mt < 4; mt++)
#pragma unroll
                for (int nt = 0; nt < 4; nt++)
                    mma16816(acc[mt][nt], ah[mt], bh[nt]);
        }

        // ---- per-row top-2 over this warp's 32 cols (branchless IMNMX) ----
#pragma unroll
        for (int mt = 0; mt < 4; mt++) {
#pragma unroll
            for (int s = 0; s < 2; s++) {
                uint32_t k1 = ~0u, k2 = ~0u;
#pragma unroll
                for (int nt = 0; nt < 4; nt++) {
#pragma unroll
                    for (int e = 0; e < 2; e++) {
                        int col = warp_n * 32 + nt * 8 + (lane & 3) * 2 + e;
                        float sc = fmaf(-2.f, acc[mt][nt][s * 2 + e], csr[nt * 2 + e]);
                        uint32_t kk = (f2ord(sc) & 0xFFFFFF80u) | (uint32_t)col;
                        k2 = umin2(k2, umax2(k1, kk));
                        k1 = umin2(k1, kk);
                    }
                }
#pragma unroll
                for (int m = 1; m < 4; m <<= 1) {
                    uint32_t o1 = __shfl_xor_sync(0xffffffffu, k1, m);
                    uint32_t o2 = __shfl_xor_sync(0xffffffffu, k2, m);
                    k2 = umin2(umin2(k2, o2), umax2(k1, o1));
                    k1 = umin2(k1, o1);
                }
                if ((lane & 3) == 0) {
                    int rloc = warp_m * 64 + mt * 16 + (lane >> 2) + s * 8;
                    keyp[rloc * 8 + warp_n * 2 + 0] = k1;
                    keyp[rloc * 8 + warp_n * 2 + 1] = k2;
                }
            }
        }
        __syncthreads();   // keyp visible; all MMA reads of A done

        // ---- fused phase: prefetch + merge/emit (warps 0-3) + convert (all) ----
        int tn = t + stride;
        bool hn = (tn < NT);
        float4 v[8];
        if (hn) {
            long long rowg = (long long)tn * TROWS + rowloc;
            if (rowg >= Brows) rowg = Brows - 1;
            load_row_quads(v, xg, rowg, g);
        }

        if (tid < TROWS) {
            uint32_t g1 = ~0u, g2 = ~0u;
#pragma unroll
            for (int w = 0; w < 4; w++) {
                uint32_t o1 = keyp[tid * 8 + w * 2 + 0];
                uint32_t o2 = keyp[tid * 8 + w * 2 + 1];
                g2 = umin2(umin2(g2, o2), umax2(g1, o1));
                g1 = umin2(g1, o1);
            }
            int j = (int)(g1 & 127u);
            long long rowg = row0 + tid;
            if (rowg < Brows) {
                float s1 = ord2f(g1 & 0xFFFFFF80u);
                float s2 = ord2f(g2 & 0xFFFFFF80u);
                float d2;
                if (s2 - s1 < REFINE_T) {
                    const float4* xp4 = reinterpret_cast<const float4*>(xg + rowg * EDIM);
                    int jb = (int)(g2 & 127u);
                    float d2a = exact_d2(xp4, reinterpret_cast<const float4*>(cg + (long long)j * EDIM));
                    float d2b = exact_d2(xp4, reinterpret_cast<const float4*>(cg + (long long)jb * EDIM));
                    if (d2b < d2a || (d2b == d2a && jb < j)) { j = jb; d2a = d2b; }
                    d2 = d2a;
                } else {
                    d2 = xsq[xb * 128 + tid] + s1;
                }
                float dist = sqrtf(fmaxf(d2, 0.f));
                float strength = expf(-dist / (rad[j] + 1e-8f));
                g_s[rowg] = 0.1f * strength;
                g_j[rowg] = j;
                if (write_idx)
                    out[(long long)Brows * EDIM + rowg] = (float)j;
            }
        }

        // convert next tile into A plane + xsq[xb^1] (overlaps merge above)
        if (hn) {
            long long base = (long long)tn * TROWS;
            long long r1c = base + rowloc + 64;
            if (r1c >= Brows) r1c = Brows - 1;
            float4 v2[8];
            load_row_quads(v2, xg, r1c, g);     // flight hides under cvt below
            float* xnext = xsq + (xb ^ 1) * 128;
            cvt_hi(sb, A_HI, rowloc, g, v, xnext);
            cvt_hi(sb, A_HI, rowloc + 64, g, v2, xnext);
        }
        __syncthreads();
        xb ^= 1;
    }
}

// ============================ kernel 2: blend =============================
__global__ void __launch_bounds__(256)
blend_kernel(const float* __restrict__ xg, const float* __restrict__ cg,
             float* __restrict__ out, int Brows)
{
    const float4* x4 = reinterpret_cast<const float4*>(xg);
    const float4* c4 = reinterpret_cast<const float4*>(cg);
    float4* o4 = reinterpret_cast<float4*>(out);
    const long long total = (long long)Brows * 32;
    const long long step = (long long)gridDim.x * blockDim.x;
    for (long long f = (long long)blockIdx.x * blockDim.x + threadIdx.x; f < total; f += step) {
        long long row = f >> 5;
        int q = (int)(f & 31);
        int j = g_j[row];          // uniform across warp -> broadcast
        float s = g_s[row];
        float om = 1.f - s;
        float4 xv = __ldg(x4 + row * 32 + q);
        float4 cv = __ldg(c4 + (long long)j * 32 + q);
        float4 o;
        o.x = fmaf(cv.x, s, xv.x * om);
        o.y = fmaf(cv.y, s, xv.y * om);
        o.z = fmaf(cv.z, s, xv.z * om);
        o.w = fmaf(cv.w, s, xv.w * om);
        o4[row * 32 + q] = o;
    }
}

extern "C" void kernel_launch(void* const* d_in, const int* in_sizes, int n_in,
                              void* d_out, int out_size)
{
    const float* x     = (const float*)d_in[0];
    const float* c     = (const float*)d_in[1];
    const float* radii = (const float*)d_in[2];
    float* out = (float*)d_out;

    int Brows = in_sizes[0] / EDIM;
    if (Brows > BMAX) Brows = BMAX;
    int write_idx = (out_size >= Brows * (EDIM + 1)) ? 1 : 0;

    int sms = 148;
    cudaDeviceGetAttribute(&sms, cudaDevAttrMultiProcessorCount, 0);
    int nt = (Brows + TROWS - 1) / TROWS;
    int grid1 = 2 * sms < nt ? 2 * sms : nt;

    cudaFuncSetAttribute(argmin_kernel,
                         cudaFuncAttributeMaxDynamicSharedMemorySize, (int)SMEM_K1);
    argmin_kernel<<<grid1, NTH, SMEM_K1>>>(x, c, radii, out, Brows, write_idx);

    int grid2 = sms * 8;
    blend_kernel<<<grid2, 256>>>(x, c, out, Brows);
}